// round 1
// baseline (speedup 1.0000x reference)
#include <cuda_runtime.h>
#include <math.h>

#define N 1024
#define EPSF 1e-8f

struct __align__(16) Geom {
    float cx, cy, cs, sn, hx, hy, rad, area;
    float x[4], y[4];
};

__device__ Geom d_geomP[N];
__device__ Geom d_geomG[N];
__device__ Geom d_geomGo[N];
__device__ int d_order[N];
__device__ unsigned int d_mask[N * 32];
__device__ int d_sampled[N];
__device__ float d_pzmin[N], d_pzmax[N], d_pvol[N];
__device__ float d_gzmin[N], d_gzmax[N], d_gvol[N];

__device__ __forceinline__ void make_geom(const float* b, Geom& g) {
    float cx = b[0], cy = b[1], dx = b[3], dy = b[4], r = b[6];
    float sn, cs;
    sincosf(r, &sn, &cs);
    float hx = 0.5f * dx, hy = 0.5f * dy;
    g.cx = cx; g.cy = cy; g.cs = cs; g.sn = sn;
    g.hx = hx; g.hy = hy;
    g.rad = 0.5f * sqrtf(dx * dx + dy * dy);
    g.area = dx * dy;
    // corners: tmpl (+.5,+.5),(+.5,-.5),(-.5,-.5),(-.5,+.5) scaled, rotated, shifted
    g.x[0] =  hx * cs - hy * sn + cx;  g.y[0] =  hx * sn + hy * cs + cy;
    g.x[1] =  hx * cs + hy * sn + cx;  g.y[1] =  hx * sn - hy * cs + cy;
    g.x[2] = -hx * cs + hy * sn + cx;  g.y[2] = -hx * sn - hy * cs + cy;
    g.x[3] = -hx * cs - hy * sn + cx;  g.y[3] = -hx * sn + hy * cs + cy;
}

__device__ __forceinline__ bool pt_in(const Geom& B, float X, float Y) {
    float qx = X - B.cx, qy = Y - B.cy;
    float lx = qx * B.cs + qy * B.sn;
    float ly = qy * B.cs - qx * B.sn;
    return (fabsf(lx) <= B.hx + 1e-5f) && (fabsf(ly) <= B.hy + 1e-5f);
}

// atan2-order-equivalent comparator: bucket by quadrant band, cross product within.
__device__ __forceinline__ bool ang_less(float ax, float ay, float bx, float by) {
    int ba = (ay < 0.f) ? 0 : ((ay > 0.f) ? 2 : ((ax >= 0.f) ? 1 : 3));
    int bb = (by < 0.f) ? 0 : ((by > 0.f) ? 2 : ((bx >= 0.f) ? 1 : 3));
    if (ba != bb) return ba < bb;
    return (ax * by - ay * bx) > 0.f;
}

__device__ float rect_inter(const Geom& A, const Geom& B) {
    // exact bounding-circle rejection (separated rects -> reference area = 0)
    {
        float ddx = A.cx - B.cx, ddy = A.cy - B.cy;
        float rr = A.rad + B.rad;
        if (ddx * ddx + ddy * ddy > rr * rr) return 0.f;
    }
    float px[24], py[24];
    int k = 0;
#pragma unroll
    for (int c = 0; c < 4; c++)
        if (pt_in(B, A.x[c], A.y[c])) { px[k] = A.x[c]; py[k] = A.y[c]; k++; }
#pragma unroll
    for (int c = 0; c < 4; c++)
        if (pt_in(A, B.x[c], B.y[c])) { px[k] = B.x[c]; py[k] = B.y[c]; k++; }
#pragma unroll
    for (int i2 = 0; i2 < 4; i2++) {
        float a0x = A.x[i2], a0y = A.y[i2];
        float d1x = A.x[(i2 + 1) & 3] - a0x, d1y = A.y[(i2 + 1) & 3] - a0y;
#pragma unroll
        for (int j2 = 0; j2 < 4; j2++) {
            float b0x = B.x[j2], b0y = B.y[j2];
            float d2x = B.x[(j2 + 1) & 3] - b0x, d2y = B.y[(j2 + 1) & 3] - b0y;
            float den = d1x * d2y - d1y * d2x;
            if (fabsf(den) > EPSF) {
                float r0x = b0x - a0x, r0y = b0y - a0y;
                float t = (r0x * d2y - r0y * d2x) / den;
                float u = (r0x * d1y - r0y * d1x) / den;
                if (t >= 0.f && t <= 1.f && u >= 0.f && u <= 1.f) {
                    px[k] = a0x + t * d1x;
                    py[k] = a0y + t * d1y;
                    k++;
                }
            }
        }
    }
    if (k < 3) return 0.f;
    float sx = 0.f, sy = 0.f;
    for (int m = 0; m < k; m++) { sx += px[m]; sy += py[m]; }
    float ctx = sx / (float)k, cty = sy / (float)k;
    for (int m = 0; m < k; m++) { px[m] -= ctx; py[m] -= cty; }
    // insertion sort by angle (same cyclic order as atan2 sort)
    for (int a = 1; a < k; a++) {
        float vx = px[a], vy = py[a];
        int b2 = a - 1;
        while (b2 >= 0 && ang_less(vx, vy, px[b2], py[b2])) {
            px[b2 + 1] = px[b2]; py[b2 + 1] = py[b2]; b2--;
        }
        px[b2 + 1] = vx; py[b2 + 1] = vy;
    }
    float s2 = 0.f;
    for (int m = 0; m < k; m++) {
        int n2 = (m + 1 < k) ? (m + 1) : 0;
        s2 += px[m] * py[n2] - py[m] * px[n2];
    }
    return 0.5f * fabsf(s2);
}

// ---------------- kernels ----------------

__global__ void prep_kernel(const float* __restrict__ pred, const float* __restrict__ gt) {
    int i = blockIdx.x * blockDim.x + threadIdx.x;
    if (i < N) {
        make_geom(pred + 7 * i, d_geomP[i]);
        float z = pred[7 * i + 2], dz = pred[7 * i + 5];
        d_pzmin[i] = z - dz * 0.5f;
        d_pzmax[i] = z + dz * 0.5f;
        d_pvol[i]  = pred[7 * i + 3] * pred[7 * i + 4] * dz;
    } else if (i < 2 * N) {
        int j = i - N;
        make_geom(gt + 8 * j, d_geomG[j]);
        float z = gt[8 * j + 2], dz = gt[8 * j + 5];
        d_gzmin[j] = z - dz * 0.5f;
        d_gzmax[j] = z + dz * 0.5f;
        d_gvol[j]  = gt[8 * j + 3] * gt[8 * j + 4] * dz;
    }
}

// single-block bitonic sort, descending by score (argsort(-scores))
__global__ void sort_kernel(const float* __restrict__ scores) {
    __shared__ float s[N];
    __shared__ int id[N];
    int t = threadIdx.x;
    s[t] = scores[t];
    id[t] = t;
    __syncthreads();
    for (int k = 2; k <= N; k <<= 1) {
        for (int j = k >> 1; j > 0; j >>= 1) {
            int ixj = t ^ j;
            if (ixj > t) {
                bool up = (t & k) == 0;
                float a = s[t], b = s[ixj];
                bool sw = up ? (a < b) : (a > b);
                if (sw) {
                    s[t] = b; s[ixj] = a;
                    int tmp = id[t]; id[t] = id[ixj]; id[ixj] = tmp;
                }
            }
            __syncthreads();
        }
    }
    d_order[t] = id[t];
}

__global__ void reorder_kernel() {
    int i = blockIdx.x * blockDim.x + threadIdx.x;
    if (i < N) d_geomGo[i] = d_geomG[d_order[i]];
}

// suppression bitmask in order-space: bit j of row i set iff IoU_bev(o_i,o_j) > 0.1
__global__ void nms_iou_kernel() {
    int i = blockIdx.x;
    Geom A = d_geomGo[i];
    float sa = A.area;
#pragma unroll
    for (int s = 0; s < 4; s++) {
        int j = threadIdx.x + 256 * s;
        Geom B = d_geomGo[j];
        float inter = rect_inter(A, B);
        float un = fmaxf(sa + B.area - inter, EPSF);
        bool bit = (inter / un) > 0.1f;
        unsigned bal = __ballot_sync(0xffffffffu, bit);
        if ((threadIdx.x & 31) == 0)
            d_mask[i * 32 + (threadIdx.x >> 5) + 8 * s] = bal;
    }
}

// serial NMS: preload mask into 128KB smem, one warp walks 1024 iterations
extern __shared__ unsigned sm_mask[];
__global__ void nms_serial_kernel() {
    for (int t = threadIdx.x; t < N * 32; t += blockDim.x)
        sm_mask[t] = d_mask[t];
    __syncthreads();
    if (threadIdx.x < 32) {
        int lane = threadIdx.x;
        unsigned kw = 0xFFFFFFFFu;  // keep bits for indices [lane*32, lane*32+31]
        for (int i = 0; i < N; i++) {
            int owner = i >> 5, bit = i & 31;
            unsigned ow = __shfl_sync(0xffffffffu, kw, owner);
            if ((ow >> bit) & 1u) {
                unsigned m = sm_mask[i * 32 + lane];
                if (lane < owner) m = 0u;
                else if (lane == owner) m &= (bit == 31) ? 0u : (0xFFFFFFFFu << (bit + 1));
                kw &= ~m;
            }
        }
#pragma unroll
        for (int b = 0; b < 32; b++) {
            int idx = lane * 32 + b;
            d_sampled[d_order[idx]] = (kw >> b) & 1u;
        }
    }
}

// pred x gt 3D IoU, row max + first-tie argmax, clamped overlaps
__global__ void iou3d_kernel(float* __restrict__ out) {
    int i = blockIdx.x;
    int t = threadIdx.x;
    Geom A = d_geomP[i];
    float amin = d_pzmin[i], amax = d_pzmax[i], va = d_pvol[i];
    float best = -1.f;
    int bidx = 0;
#pragma unroll
    for (int s = 0; s < 4; s++) {
        int j = t + 256 * s;
        float iou = 0.f;
        if (d_sampled[j]) {
            float oh = fminf(amax, d_gzmax[j]) - fmaxf(amin, d_gzmin[j]);
            if (oh > 0.f) {
                Geom B = d_geomG[j];
                float inter = rect_inter(A, B) * oh;
                float un = fmaxf(va + d_gvol[j] - inter, EPSF);
                iou = inter / un;
            }
        }
        if (iou > best) { best = iou; bidx = j; }
    }
    __shared__ float sv[256];
    __shared__ int si[256];
    sv[t] = best; si[t] = bidx;
    __syncthreads();
    for (int off = 128; off > 0; off >>= 1) {
        if (t < off) {
            float v2 = sv[t + off];
            int i2 = si[t + off];
            if (v2 > sv[t] || (v2 == sv[t] && i2 < si[t])) { sv[t] = v2; si[t] = i2; }
        }
        __syncthreads();
    }
    if (t == 0) {
        float mo = sv[0];
        mo = (mo > 0.75f) ? 1.0f : ((mo < 0.25f) ? 0.0f : mo);
        out[2 * N + i] = mo;
        out[3 * N + i] = (float)si[0];
    }
}

__global__ void finalize_kernel(const float* __restrict__ labels,
                                const float* __restrict__ cls,
                                float* __restrict__ out) {
    int i = blockIdx.x * blockDim.x + threadIdx.x;
    if (i >= N) return;
    float cp = 1.f / (1.f + expf(-cls[i]));
    out[i]     = (cp > 0.55f && labels[i] > 0.55f) ? 1.0f : 0.0f;
    out[N + i] = labels[i];
}

extern "C" void kernel_launch(void* const* d_in, const int* in_sizes, int n_in,
                              void* d_out, int out_size) {
    const float* labels = (const float*)d_in[0];
    const float* pred   = (const float*)d_in[1];
    const float* gt     = (const float*)d_in[2];
    const float* cls    = (const float*)d_in[3];
    // defensive: pred has 7 cols (7168 elems), gt has 8 cols (8192 elems)
    if (n_in >= 3 && in_sizes[1] == 8 * N && in_sizes[2] == 7 * N) {
        pred = (const float*)d_in[2];
        gt   = (const float*)d_in[1];
    }
    float* out = (float*)d_out;

    prep_kernel<<<(2 * N + 255) / 256, 256>>>(pred, gt);
    sort_kernel<<<1, N>>>(labels);
    reorder_kernel<<<(N + 255) / 256, 256>>>();
    nms_iou_kernel<<<N, 256>>>();
    cudaFuncSetAttribute(nms_serial_kernel,
                         cudaFuncAttributeMaxDynamicSharedMemorySize, N * 32 * 4);
    nms_serial_kernel<<<1, 1024, N * 32 * 4>>>();
    iou3d_kernel<<<N, 256>>>(out);
    finalize_kernel<<<(N + 255) / 256, 256>>>(labels, cls, out);
}

// round 2
// speedup vs baseline: 2.6121x; 2.6121x over previous
#include <cuda_runtime.h>
#include <math.h>

#define N 1024
#define EPSF 1e-8f

struct __align__(16) Geom {
    float cx, cy, cs, sn, hx, hy, rad, area;
    float x[4], y[4];
};

__device__ Geom d_geomP[N];
__device__ Geom d_geomG[N];
__device__ Geom d_geomGo[N];
__device__ float4 d_ccP[N];   // cx, cy, rad, unused
__device__ float4 d_ccG[N];
__device__ float4 d_ccGo[N];
__device__ int d_order[N];
__device__ unsigned int d_mask[N * 32];
__device__ int d_sampled[N];
__device__ float d_pzmin[N], d_pzmax[N], d_pvol[N];
__device__ float d_gzmin[N], d_gzmax[N], d_gvol[N];
__device__ unsigned long long d_best[N];
__device__ int d_nms_cnt;
__device__ int d_iou_cnt;
__device__ int d_nms_pairs[N * N / 2];
__device__ int d_iou_pairs[N * N];

__device__ __forceinline__ void make_geom(const float* b, Geom& g) {
    float cx = b[0], cy = b[1], dx = b[3], dy = b[4], r = b[6];
    float sn, cs;
    sincosf(r, &sn, &cs);
    float hx = 0.5f * dx, hy = 0.5f * dy;
    g.cx = cx; g.cy = cy; g.cs = cs; g.sn = sn;
    g.hx = hx; g.hy = hy;
    g.rad = 0.5f * sqrtf(dx * dx + dy * dy);
    g.area = dx * dy;
    g.x[0] =  hx * cs - hy * sn + cx;  g.y[0] =  hx * sn + hy * cs + cy;
    g.x[1] =  hx * cs + hy * sn + cx;  g.y[1] =  hx * sn - hy * cs + cy;
    g.x[2] = -hx * cs + hy * sn + cx;  g.y[2] = -hx * sn - hy * cs + cy;
    g.x[3] = -hx * cs - hy * sn + cx;  g.y[3] = -hx * sn + hy * cs + cy;
}

__device__ __forceinline__ bool pt_in(const Geom& B, float X, float Y) {
    float qx = X - B.cx, qy = Y - B.cy;
    float lx = qx * B.cs + qy * B.sn;
    float ly = qy * B.cs - qx * B.sn;
    return (fabsf(lx) <= B.hx + 1e-5f) && (fabsf(ly) <= B.hy + 1e-5f);
}

__device__ __forceinline__ bool ang_less(float ax, float ay, float bx, float by) {
    int ba = (ay < 0.f) ? 0 : ((ay > 0.f) ? 2 : ((ax >= 0.f) ? 1 : 3));
    int bb = (by < 0.f) ? 0 : ((by > 0.f) ? 2 : ((bx >= 0.f) ? 1 : 3));
    if (ba != bb) return ba < bb;
    return (ax * by - ay * bx) > 0.f;
}

// full polygon clip — only called on circle-test survivors
__device__ float rect_inter_full(const Geom& A, const Geom& B) {
    float px[24], py[24];
    int k = 0;
#pragma unroll
    for (int c = 0; c < 4; c++)
        if (pt_in(B, A.x[c], A.y[c])) { px[k] = A.x[c]; py[k] = A.y[c]; k++; }
#pragma unroll
    for (int c = 0; c < 4; c++)
        if (pt_in(A, B.x[c], B.y[c])) { px[k] = B.x[c]; py[k] = B.y[c]; k++; }
#pragma unroll
    for (int i2 = 0; i2 < 4; i2++) {
        float a0x = A.x[i2], a0y = A.y[i2];
        float d1x = A.x[(i2 + 1) & 3] - a0x, d1y = A.y[(i2 + 1) & 3] - a0y;
#pragma unroll
        for (int j2 = 0; j2 < 4; j2++) {
            float b0x = B.x[j2], b0y = B.y[j2];
            float d2x = B.x[(j2 + 1) & 3] - b0x, d2y = B.y[(j2 + 1) & 3] - b0y;
            float den = d1x * d2y - d1y * d2x;
            if (fabsf(den) > EPSF) {
                float r0x = b0x - a0x, r0y = b0y - a0y;
                float t = (r0x * d2y - r0y * d2x) / den;
                float u = (r0x * d1y - r0y * d1x) / den;
                if (t >= 0.f && t <= 1.f && u >= 0.f && u <= 1.f) {
                    px[k] = a0x + t * d1x;
                    py[k] = a0y + t * d1y;
                    k++;
                }
            }
        }
    }
    if (k < 3) return 0.f;
    float sx = 0.f, sy = 0.f;
    for (int m = 0; m < k; m++) { sx += px[m]; sy += py[m]; }
    float ctx = sx / (float)k, cty = sy / (float)k;
    for (int m = 0; m < k; m++) { px[m] -= ctx; py[m] -= cty; }
    for (int a = 1; a < k; a++) {
        float vx = px[a], vy = py[a];
        int b2 = a - 1;
        while (b2 >= 0 && ang_less(vx, vy, px[b2], py[b2])) {
            px[b2 + 1] = px[b2]; py[b2 + 1] = py[b2]; b2--;
        }
        px[b2 + 1] = vx; py[b2 + 1] = vy;
    }
    float s2 = 0.f;
    for (int m = 0; m < k; m++) {
        int n2 = (m + 1 < k) ? (m + 1) : 0;
        s2 += px[m] * py[n2] - py[m] * px[n2];
    }
    return 0.5f * fabsf(s2);
}

// ---------------- kernels ----------------

__global__ void prep_kernel(const float* __restrict__ pred, const float* __restrict__ gt) {
    int i = blockIdx.x * blockDim.x + threadIdx.x;
    if (i == 0) { d_nms_cnt = 0; d_iou_cnt = 0; }
    if (i < N) {
        make_geom(pred + 7 * i, d_geomP[i]);
        Geom& g = d_geomP[i];
        d_ccP[i] = make_float4(g.cx, g.cy, g.rad, 0.f);
        float z = pred[7 * i + 2], dz = pred[7 * i + 5];
        d_pzmin[i] = z - dz * 0.5f;
        d_pzmax[i] = z + dz * 0.5f;
        d_pvol[i]  = pred[7 * i + 3] * pred[7 * i + 4] * dz;
        d_best[i] = 0xFFFFFFFFull;  // iou=0.0, j=0
    } else if (i < 2 * N) {
        int j = i - N;
        make_geom(gt + 8 * j, d_geomG[j]);
        Geom& g = d_geomG[j];
        d_ccG[j] = make_float4(g.cx, g.cy, g.rad, 0.f);
        float z = gt[8 * j + 2], dz = gt[8 * j + 5];
        d_gzmin[j] = z - dz * 0.5f;
        d_gzmax[j] = z + dz * 0.5f;
        d_gvol[j]  = gt[8 * j + 3] * gt[8 * j + 4] * dz;
    }
}

// bitonic argsort (descending) + fused reorder of gt geoms into order space
__global__ void sort_kernel(const float* __restrict__ scores) {
    __shared__ float s[N];
    __shared__ int id[N];
    int t = threadIdx.x;
    s[t] = scores[t];
    id[t] = t;
    __syncthreads();
    for (int k = 2; k <= N; k <<= 1) {
        for (int j = k >> 1; j > 0; j >>= 1) {
            int ixj = t ^ j;
            if (ixj > t) {
                bool up = (t & k) == 0;
                float a = s[t], b = s[ixj];
                bool sw = up ? (a < b) : (a > b);
                if (sw) {
                    s[t] = b; s[ixj] = a;
                    int tmp = id[t]; id[t] = id[ixj]; id[ixj] = tmp;
                }
            }
            __syncthreads();
        }
    }
    int src = id[t];
    d_order[t] = src;
    Geom g = d_geomG[src];
    d_geomGo[t] = g;
    d_ccGo[t] = make_float4(g.cx, g.cy, g.rad, 0.f);
}

// Phase A (NMS): circle test on upper triangle, queue survivors, zero own mask row
__global__ void nms_pairgen_kernel() {
    int i = blockIdx.x;
    int t = threadIdx.x;
    if (t < 32) d_mask[i * 32 + t] = 0u;
    float4 ci = d_ccGo[i];
#pragma unroll
    for (int s = 0; s < 4; s++) {
        int j = t + 256 * s;
        bool pass = false;
        if (j > i) {
            float4 cj = d_ccGo[j];
            float dx = ci.x - cj.x, dy = ci.y - cj.y;
            float rr = ci.z + cj.z;
            pass = (dx * dx + dy * dy <= rr * rr);
        }
        unsigned bal = __ballot_sync(0xffffffffu, pass);
        if (bal) {
            int leader = __ffs(bal) - 1;
            int lane = t & 31;
            int base = 0;
            if (lane == leader) base = atomicAdd(&d_nms_cnt, __popc(bal));
            base = __shfl_sync(0xffffffffu, base, leader);
            if (pass) {
                int ofs = __popc(bal & ((1u << lane) - 1u));
                d_nms_pairs[base + ofs] = (i << 10) | j;
            }
        }
    }
}

// Phase B (NMS): full clip on survivors, set suppression bits
__global__ void nms_process_kernel() {
    int cnt = d_nms_cnt;
    int stride = gridDim.x * blockDim.x;
    for (int idx = blockIdx.x * blockDim.x + threadIdx.x; idx < cnt; idx += stride) {
        int pr = d_nms_pairs[idx];
        int i = pr >> 10, j = pr & 1023;
        Geom A = d_geomGo[i];
        Geom B = d_geomGo[j];
        float inter = rect_inter_full(A, B);
        float un = fmaxf(A.area + B.area - inter, EPSF);
        if (inter / un > 0.1f)
            atomicOr(&d_mask[i * 32 + (j >> 5)], 1u << (j & 31));
    }
}

// serial NMS: mask in smem, one warp walks 1024 iterations
extern __shared__ unsigned sm_mask[];
__global__ void nms_serial_kernel() {
    for (int t = threadIdx.x; t < N * 32; t += blockDim.x)
        sm_mask[t] = d_mask[t];
    __syncthreads();
    if (threadIdx.x < 32) {
        int lane = threadIdx.x;
        unsigned kw = 0xFFFFFFFFu;
        for (int i = 0; i < N; i++) {
            int owner = i >> 5, bit = i & 31;
            unsigned ow = __shfl_sync(0xffffffffu, kw, owner);
            if ((ow >> bit) & 1u) {
                unsigned m = sm_mask[i * 32 + lane];
                if (lane < owner) m = 0u;
                else if (lane == owner) m &= (bit == 31) ? 0u : (0xFFFFFFFFu << (bit + 1));
                kw &= ~m;
            }
        }
#pragma unroll
        for (int b = 0; b < 32; b++) {
            int idx = lane * 32 + b;
            d_sampled[d_order[idx]] = (kw >> b) & 1u;
        }
    }
}

// Phase A (iou3d): sampled + z-overlap + circle test, queue survivors
__global__ void iou_pairgen_kernel() {
    int i = blockIdx.x;
    int t = threadIdx.x;
    float4 ci = d_ccP[i];
    float amin = d_pzmin[i], amax = d_pzmax[i];
#pragma unroll
    for (int s = 0; s < 4; s++) {
        int j = t + 256 * s;
        bool pass = false;
        if (d_sampled[j]) {
            float oh = fminf(amax, d_gzmax[j]) - fmaxf(amin, d_gzmin[j]);
            if (oh > 0.f) {
                float4 cj = d_ccG[j];
                float dx = ci.x - cj.x, dy = ci.y - cj.y;
                float rr = ci.z + cj.z;
                pass = (dx * dx + dy * dy <= rr * rr);
            }
        }
        unsigned bal = __ballot_sync(0xffffffffu, pass);
        if (bal) {
            int leader = __ffs(bal) - 1;
            int lane = t & 31;
            int base = 0;
            if (lane == leader) base = atomicAdd(&d_iou_cnt, __popc(bal));
            base = __shfl_sync(0xffffffffu, base, leader);
            if (pass) {
                int ofs = __popc(bal & ((1u << lane) - 1u));
                d_iou_pairs[base + ofs] = (i << 10) | j;
            }
        }
    }
}

// Phase B (iou3d): full clip on survivors, packed atomicMax per pred row.
// key = (iou_bits << 32) | (0xFFFFFFFF - j)  ->  max iou, ties -> smallest j
__global__ void iou_process_kernel() {
    int cnt = d_iou_cnt;
    int stride = gridDim.x * blockDim.x;
    for (int idx = blockIdx.x * blockDim.x + threadIdx.x; idx < cnt; idx += stride) {
        int pr = d_iou_pairs[idx];
        int i = pr >> 10, j = pr & 1023;
        Geom A = d_geomP[i];
        Geom B = d_geomG[j];
        float oh = fminf(d_pzmax[i], d_gzmax[j]) - fmaxf(d_pzmin[i], d_gzmin[j]);
        float inter = rect_inter_full(A, B) * oh;
        float un = fmaxf(d_pvol[i] + d_gvol[j] - inter, EPSF);
        float iou = inter / un;
        if (iou > 0.f) {
            unsigned long long key =
                (((unsigned long long)__float_as_uint(iou)) << 32) |
                (unsigned long long)(0xFFFFFFFFu - (unsigned)j);
            atomicMax(&d_best[i], key);
        }
    }
}

__global__ void finalize_kernel(const float* __restrict__ labels,
                                const float* __restrict__ cls,
                                float* __restrict__ out) {
    int i = blockIdx.x * blockDim.x + threadIdx.x;
    if (i >= N) return;
    float cp = 1.f / (1.f + expf(-cls[i]));
    out[i]     = (cp > 0.55f && labels[i] > 0.55f) ? 1.0f : 0.0f;
    out[N + i] = labels[i];
    unsigned long long key = d_best[i];
    float mo = __uint_as_float((unsigned)(key >> 32));
    int j = (int)(0xFFFFFFFFu - (unsigned)(key & 0xFFFFFFFFull));
    mo = (mo > 0.75f) ? 1.0f : ((mo < 0.25f) ? 0.0f : mo);
    out[2 * N + i] = mo;
    out[3 * N + i] = (float)j;
}

extern "C" void kernel_launch(void* const* d_in, const int* in_sizes, int n_in,
                              void* d_out, int out_size) {
    const float* labels = (const float*)d_in[0];
    const float* pred   = (const float*)d_in[1];
    const float* gt     = (const float*)d_in[2];
    const float* cls    = (const float*)d_in[3];
    if (n_in >= 3 && in_sizes[1] == 8 * N && in_sizes[2] == 7 * N) {
        pred = (const float*)d_in[2];
        gt   = (const float*)d_in[1];
    }
    float* out = (float*)d_out;

    prep_kernel<<<(2 * N + 255) / 256, 256>>>(pred, gt);
    sort_kernel<<<1, N>>>(labels);
    nms_pairgen_kernel<<<N, 256>>>();
    nms_process_kernel<<<256, 256>>>();
    cudaFuncSetAttribute(nms_serial_kernel,
                         cudaFuncAttributeMaxDynamicSharedMemorySize, N * 32 * 4);
    nms_serial_kernel<<<1, 1024, N * 32 * 4>>>();
    iou_pairgen_kernel<<<N, 256>>>();
    iou_process_kernel<<<256, 256>>>();
    finalize_kernel<<<(N + 255) / 256, 256>>>(labels, cls, out);
}

// round 3
// speedup vs baseline: 3.9768x; 1.5225x over previous
#include <cuda_runtime.h>
#include <math.h>

#define N 1024
#define EPSF 1e-8f

struct __align__(16) Geom {
    float cx, cy, cs, sn, hx, hy, rad, area;
    float x[4], y[4];
};

__device__ Geom d_geomP[N];
__device__ Geom d_geomG[N];
__device__ Geom d_geomGo[N];
__device__ float4 d_ccP[N];
__device__ float4 d_ccG[N];
__device__ float4 d_ccGo[N];
__device__ int d_order[N];
__device__ unsigned int d_mask[N * 32];
__device__ int d_sampled[N];
__device__ float d_pzmin[N], d_pzmax[N], d_pvol[N];
__device__ float d_gzmin[N], d_gzmax[N], d_gvol[N];
__device__ unsigned long long d_best[N];
__device__ int d_nms_cnt;
__device__ int d_iou_cnt;
__device__ int d_nms_pairs[N * N / 2];
__device__ int d_iou_pairs[N * N];

__device__ __forceinline__ void make_geom(const float* b, Geom& g) {
    float cx = b[0], cy = b[1], dx = b[3], dy = b[4], r = b[6];
    float sn, cs;
    sincosf(r, &sn, &cs);
    float hx = 0.5f * dx, hy = 0.5f * dy;
    g.cx = cx; g.cy = cy; g.cs = cs; g.sn = sn;
    g.hx = hx; g.hy = hy;
    g.rad = 0.5f * sqrtf(dx * dx + dy * dy);
    g.area = dx * dy;
    g.x[0] =  hx * cs - hy * sn + cx;  g.y[0] =  hx * sn + hy * cs + cy;
    g.x[1] =  hx * cs + hy * sn + cx;  g.y[1] =  hx * sn - hy * cs + cy;
    g.x[2] = -hx * cs + hy * sn + cx;  g.y[2] = -hx * sn - hy * cs + cy;
    g.x[3] = -hx * cs - hy * sn + cx;  g.y[3] = -hx * sn + hy * cs + cy;
}

// Sutherland–Hodgman: clip B's corners (CW) by A's 4 edges (CW rect,
// interior = cross(edge, p - v0) <= 0). Same convex polygon as the
// reference's candidate-point construction -> identical area up to fp.
__device__ float rect_inter_sh(const Geom& A, const Geom& B) {
    float qx[8], qy[8];
    int n = 4;
#pragma unroll
    for (int c = 0; c < 4; c++) { qx[c] = B.x[c]; qy[c] = B.y[c]; }
#pragma unroll
    for (int e = 0; e < 4; e++) {
        float x0 = A.x[e], y0 = A.y[e];
        float ex = A.x[(e + 1) & 3] - x0, ey = A.y[(e + 1) & 3] - y0;
        float rx[8], ry[8];
        int m = 0;
        float sxp = qx[n - 1], syp = qy[n - 1];
        float dp = ex * (syp - y0) - ey * (sxp - x0);
        for (int v = 0; v < n; v++) {
            float cxv = qx[v], cyv = qy[v];
            float dc = ex * (cyv - y0) - ey * (cxv - x0);
            bool inp = dp <= 0.f, inc = dc <= 0.f;
            if (inp != inc) {
                float t = dp / (dp - dc);
                rx[m] = sxp + t * (cxv - sxp);
                ry[m] = syp + t * (cyv - syp);
                m++;
            }
            if (inc) { rx[m] = cxv; ry[m] = cyv; m++; }
            sxp = cxv; syp = cyv; dp = dc;
        }
        n = m;
        if (n == 0) return 0.f;
        for (int v = 0; v < n; v++) { qx[v] = rx[v]; qy[v] = ry[v]; }
    }
    float s2 = 0.f;
    for (int v = 0; v < n; v++) {
        int w = (v + 1 < n) ? (v + 1) : 0;
        s2 += qx[v] * qy[w] - qy[v] * qx[w];
    }
    return 0.5f * fabsf(s2);
}

// ---------------- kernels ----------------

// blocks [0,1024): rank of gt element b (stable descending argsort) + write
//                  order-space geom directly.
// blocks [1024,1032): per-box prep for pred (i<N) and gt (i>=N).
__global__ void prep_rank_kernel(const float* __restrict__ pred,
                                 const float* __restrict__ gt,
                                 const float* __restrict__ scores) {
    int b = blockIdx.x;
    int t = threadIdx.x;
    if (b < N) {
        __shared__ int cnt;
        if (t == 0) cnt = 0;
        __syncthreads();
        float si = scores[b];
        int c = 0;
#pragma unroll
        for (int s = 0; s < 4; s++) {
            int j = t + 256 * s;
            float sj = scores[j];
            c += (sj > si) || (sj == si && j < b);
        }
        c += __shfl_down_sync(0xffffffffu, c, 16);
        c += __shfl_down_sync(0xffffffffu, c, 8);
        c += __shfl_down_sync(0xffffffffu, c, 4);
        c += __shfl_down_sync(0xffffffffu, c, 2);
        c += __shfl_down_sync(0xffffffffu, c, 1);
        if ((t & 31) == 0) atomicAdd(&cnt, c);
        __syncthreads();
        if (t == 0) {
            int r = cnt;
            d_order[r] = b;
            Geom g;
            make_geom(gt + 8 * b, g);
            d_geomGo[r] = g;
            d_ccGo[r] = make_float4(g.cx, g.cy, g.rad, 0.f);
        }
    } else {
        int i = (b - N) * 256 + t;  // 0..2047
        if (b == N && t == 0) { d_nms_cnt = 0; d_iou_cnt = 0; }
        if (i < N) {
            make_geom(pred + 7 * i, d_geomP[i]);
            Geom& g = d_geomP[i];
            d_ccP[i] = make_float4(g.cx, g.cy, g.rad, 0.f);
            float z = pred[7 * i + 2], dz = pred[7 * i + 5];
            d_pzmin[i] = z - dz * 0.5f;
            d_pzmax[i] = z + dz * 0.5f;
            d_pvol[i]  = pred[7 * i + 3] * pred[7 * i + 4] * dz;
            d_best[i] = 0xFFFFFFFFull;  // iou=0.0, j=0
        } else {
            int j = i - N;
            make_geom(gt + 8 * j, d_geomG[j]);
            Geom& g = d_geomG[j];
            d_ccG[j] = make_float4(g.cx, g.cy, g.rad, 0.f);
            float z = gt[8 * j + 2], dz = gt[8 * j + 5];
            d_gzmin[j] = z - dz * 0.5f;
            d_gzmax[j] = z + dz * 0.5f;
            d_gvol[j]  = gt[8 * j + 3] * gt[8 * j + 4] * dz;
        }
    }
}

__device__ __forceinline__ void queue_pair(bool pass, int* q, int* cnt,
                                           int i, int j, int lane) {
    unsigned bal = __ballot_sync(0xffffffffu, pass);
    if (bal) {
        int leader = __ffs(bal) - 1;
        int base = 0;
        if (lane == leader) base = atomicAdd(cnt, __popc(bal));
        base = __shfl_sync(0xffffffffu, base, leader);
        if (pass) {
            int ofs = __popc(bal & ((1u << lane) - 1u));
            q[base + ofs] = (i << 10) | j;
        }
    }
}

// blocks [0,1024): NMS circle test (order space, j>i), zero own mask row.
// blocks [1024,2048): iou z-overlap + circle test (NO sampled filter here).
__global__ void pairgen_kernel() {
    int row = blockIdx.x;
    int t = threadIdx.x;
    int lane = t & 31;
    if (row < N) {
        int i = row;
        if (t < 32) d_mask[i * 32 + t] = 0u;
        float4 ci = d_ccGo[i];
#pragma unroll
        for (int s = 0; s < 4; s++) {
            int j = t + 256 * s;
            bool pass = false;
            if (j > i) {
                float4 cj = d_ccGo[j];
                float dx = ci.x - cj.x, dy = ci.y - cj.y;
                float rr = ci.z + cj.z;
                pass = (dx * dx + dy * dy <= rr * rr);
            }
            queue_pair(pass, d_nms_pairs, &d_nms_cnt, i, j, lane);
        }
    } else {
        int i = row - N;
        float4 ci = d_ccP[i];
        float amin = d_pzmin[i], amax = d_pzmax[i];
#pragma unroll
        for (int s = 0; s < 4; s++) {
            int j = t + 256 * s;
            float oh = fminf(amax, d_gzmax[j]) - fmaxf(amin, d_gzmin[j]);
            bool pass = false;
            if (oh > 0.f) {
                float4 cj = d_ccG[j];
                float dx = ci.x - cj.x, dy = ci.y - cj.y;
                float rr = ci.z + cj.z;
                pass = (dx * dx + dy * dy <= rr * rr);
            }
            queue_pair(pass, d_iou_pairs, &d_iou_cnt, i, j, lane);
        }
    }
}

__global__ void nms_process_kernel() {
    int cnt = d_nms_cnt;
    int stride = gridDim.x * blockDim.x;
    for (int idx = blockIdx.x * blockDim.x + threadIdx.x; idx < cnt; idx += stride) {
        int pr = d_nms_pairs[idx];
        int i = pr >> 10, j = pr & 1023;
        Geom A = d_geomGo[i];
        Geom B = d_geomGo[j];
        float inter = rect_inter_sh(A, B);
        float un = fmaxf(A.area + B.area - inter, EPSF);
        if (inter / un > 0.1f)
            atomicOr(&d_mask[i * 32 + (j >> 5)], 1u << (j & 31));
    }
}

// serial NMS, skipping suppressed boxes via ffs over live keep bits.
// mask rows only contain j>i bits, so suppression is just kw &= ~mask.
extern __shared__ unsigned sm_mask[];
__global__ void nms_serial_kernel() {
    for (int t = threadIdx.x; t < N * 32; t += blockDim.x)
        sm_mask[t] = d_mask[t];
    __syncthreads();
    if (threadIdx.x < 32) {
        int lane = threadIdx.x;
        unsigned kw = 0xFFFFFFFFu;
        for (int w = 0; w < 32; w++) {
            unsigned rem = __shfl_sync(0xffffffffu, kw, w);
            while (rem) {
                int bit = __ffs(rem) - 1;
                int i = w * 32 + bit;
                kw &= ~sm_mask[i * 32 + lane];
                unsigned cur = __shfl_sync(0xffffffffu, kw, w);
                rem = (bit == 31) ? 0u : (cur & (0xFFFFFFFFu << (bit + 1)));
            }
        }
#pragma unroll
        for (int b = 0; b < 32; b++) {
            int idx = lane * 32 + b;
            d_sampled[d_order[idx]] = (kw >> b) & 1u;
        }
    }
}

// full clip on survivors (sampled filter applied here), packed atomicMax.
// key = (iou_bits << 32) | (0xFFFFFFFF - j) -> max iou, ties -> smallest j
__global__ void iou_process_kernel() {
    int cnt = d_iou_cnt;
    int stride = gridDim.x * blockDim.x;
    for (int idx = blockIdx.x * blockDim.x + threadIdx.x; idx < cnt; idx += stride) {
        int pr = d_iou_pairs[idx];
        int i = pr >> 10, j = pr & 1023;
        if (!d_sampled[j]) continue;
        Geom A = d_geomP[i];
        Geom B = d_geomG[j];
        float oh = fminf(d_pzmax[i], d_gzmax[j]) - fmaxf(d_pzmin[i], d_gzmin[j]);
        float inter = rect_inter_sh(A, B) * oh;
        float un = fmaxf(d_pvol[i] + d_gvol[j] - inter, EPSF);
        float iou = inter / un;
        if (iou > 0.f) {
            unsigned long long key =
                (((unsigned long long)__float_as_uint(iou)) << 32) |
                (unsigned long long)(0xFFFFFFFFu - (unsigned)j);
            atomicMax(&d_best[i], key);
        }
    }
}

__global__ void finalize_kernel(const float* __restrict__ labels,
                                const float* __restrict__ cls,
                                float* __restrict__ out) {
    int i = blockIdx.x * blockDim.x + threadIdx.x;
    if (i >= N) return;
    float cp = 1.f / (1.f + expf(-cls[i]));
    out[i]     = (cp > 0.55f && labels[i] > 0.55f) ? 1.0f : 0.0f;
    out[N + i] = labels[i];
    unsigned long long key = d_best[i];
    float mo = __uint_as_float((unsigned)(key >> 32));
    int j = (int)(0xFFFFFFFFu - (unsigned)(key & 0xFFFFFFFFull));
    mo = (mo > 0.75f) ? 1.0f : ((mo < 0.25f) ? 0.0f : mo);
    out[2 * N + i] = mo;
    out[3 * N + i] = (float)j;
}

extern "C" void kernel_launch(void* const* d_in, const int* in_sizes, int n_in,
                              void* d_out, int out_size) {
    const float* labels = (const float*)d_in[0];
    const float* pred   = (const float*)d_in[1];
    const float* gt     = (const float*)d_in[2];
    const float* cls    = (const float*)d_in[3];
    if (n_in >= 3 && in_sizes[1] == 8 * N && in_sizes[2] == 7 * N) {
        pred = (const float*)d_in[2];
        gt   = (const float*)d_in[1];
    }
    float* out = (float*)d_out;

    prep_rank_kernel<<<N + 8, 256>>>(pred, gt, labels);
    pairgen_kernel<<<2 * N, 256>>>();
    nms_process_kernel<<<256, 256>>>();
    cudaFuncSetAttribute(nms_serial_kernel,
                         cudaFuncAttributeMaxDynamicSharedMemorySize, N * 32 * 4);
    nms_serial_kernel<<<1, 1024, N * 32 * 4>>>();
    iou_process_kernel<<<256, 256>>>();
    finalize_kernel<<<(N + 255) / 256, 256>>>(labels, cls, out);
}

// round 4
// speedup vs baseline: 4.6612x; 1.1721x over previous
#include <cuda_runtime.h>
#include <math.h>

#define N 1024
#define EPSF 1e-8f

struct __align__(16) Geom {
    float cx, cy, cs, sn, hx, hy, rad, area;
    float x[4], y[4];
};

__device__ Geom d_geomP[N];
__device__ Geom d_geomG[N];
__device__ Geom d_geomGo[N];
__device__ float4 d_ccP[N];
__device__ float4 d_ccG[N];
__device__ float4 d_ccGo[N];
__device__ int d_order[N];
__device__ unsigned int d_maskT[N * 32];   // column-major: in-edges of box j (i<j)
__device__ int d_sampled[N];
__device__ float d_pzmin[N], d_pzmax[N], d_pvol[N];
__device__ float d_gzmin[N], d_gzmax[N], d_gvol[N];
__device__ unsigned long long d_best[N];
__device__ int d_nms_cnt;
__device__ int d_iou_cnt;
__device__ int d_nms_pairs[N * N / 2];
__device__ int d_iou_pairs[N * N];

__device__ __forceinline__ void make_geom(const float* b, Geom& g) {
    float cx = b[0], cy = b[1], dx = b[3], dy = b[4], r = b[6];
    float sn, cs;
    sincosf(r, &sn, &cs);
    float hx = 0.5f * dx, hy = 0.5f * dy;
    g.cx = cx; g.cy = cy; g.cs = cs; g.sn = sn;
    g.hx = hx; g.hy = hy;
    g.rad = 0.5f * sqrtf(dx * dx + dy * dy);
    g.area = dx * dy;
    g.x[0] =  hx * cs - hy * sn + cx;  g.y[0] =  hx * sn + hy * cs + cy;
    g.x[1] =  hx * cs + hy * sn + cx;  g.y[1] =  hx * sn - hy * cs + cy;
    g.x[2] = -hx * cs + hy * sn + cx;  g.y[2] = -hx * sn - hy * cs + cy;
    g.x[3] = -hx * cs - hy * sn + cx;  g.y[3] = -hx * sn + hy * cs + cy;
}

// Sutherland–Hodgman clip of B by A's 4 half-planes (CW rect, interior <= 0).
__device__ float rect_inter_sh(const Geom& A, const Geom& B) {
    float qx[8], qy[8];
    int n = 4;
#pragma unroll
    for (int c = 0; c < 4; c++) { qx[c] = B.x[c]; qy[c] = B.y[c]; }
#pragma unroll
    for (int e = 0; e < 4; e++) {
        float x0 = A.x[e], y0 = A.y[e];
        float ex = A.x[(e + 1) & 3] - x0, ey = A.y[(e + 1) & 3] - y0;
        float rx[8], ry[8];
        int m = 0;
        float sxp = qx[n - 1], syp = qy[n - 1];
        float dp = ex * (syp - y0) - ey * (sxp - x0);
        for (int v = 0; v < n; v++) {
            float cxv = qx[v], cyv = qy[v];
            float dc = ex * (cyv - y0) - ey * (cxv - x0);
            bool inp = dp <= 0.f, inc = dc <= 0.f;
            if (inp != inc) {
                float t = dp / (dp - dc);
                rx[m] = sxp + t * (cxv - sxp);
                ry[m] = syp + t * (cyv - syp);
                m++;
            }
            if (inc) { rx[m] = cxv; ry[m] = cyv; m++; }
            sxp = cxv; syp = cyv; dp = dc;
        }
        n = m;
        if (n == 0) return 0.f;
        for (int v = 0; v < n; v++) { qx[v] = rx[v]; qy[v] = ry[v]; }
    }
    float s2 = 0.f;
    for (int v = 0; v < n; v++) {
        int w = (v + 1 < n) ? (v + 1) : 0;
        s2 += qx[v] * qy[w] - qy[v] * qx[w];
    }
    return 0.5f * fabsf(s2);
}

// ---------------- kernels ----------------

__global__ void prep_rank_kernel(const float* __restrict__ pred,
                                 const float* __restrict__ gt,
                                 const float* __restrict__ scores) {
    int b = blockIdx.x;
    int t = threadIdx.x;
    if (b < N) {
        __shared__ int cnt;
        if (t == 0) cnt = 0;
        __syncthreads();
        float si = scores[b];
        int c = 0;
#pragma unroll
        for (int s = 0; s < 4; s++) {
            int j = t + 256 * s;
            float sj = scores[j];
            c += (sj > si) || (sj == si && j < b);
        }
        c += __shfl_down_sync(0xffffffffu, c, 16);
        c += __shfl_down_sync(0xffffffffu, c, 8);
        c += __shfl_down_sync(0xffffffffu, c, 4);
        c += __shfl_down_sync(0xffffffffu, c, 2);
        c += __shfl_down_sync(0xffffffffu, c, 1);
        if ((t & 31) == 0) atomicAdd(&cnt, c);
        __syncthreads();
        if (t == 0) {
            int r = cnt;
            d_order[r] = b;
            Geom g;
            make_geom(gt + 8 * b, g);
            d_geomGo[r] = g;
            d_ccGo[r] = make_float4(g.cx, g.cy, g.rad, 0.f);
        }
    } else {
        int i = (b - N) * 256 + t;  // 0..2047
        if (b == N && t == 0) { d_nms_cnt = 0; d_iou_cnt = 0; }
        if (i < N) {
            make_geom(pred + 7 * i, d_geomP[i]);
            Geom& g = d_geomP[i];
            d_ccP[i] = make_float4(g.cx, g.cy, g.rad, 0.f);
            float z = pred[7 * i + 2], dz = pred[7 * i + 5];
            d_pzmin[i] = z - dz * 0.5f;
            d_pzmax[i] = z + dz * 0.5f;
            d_pvol[i]  = pred[7 * i + 3] * pred[7 * i + 4] * dz;
            d_best[i] = 0xFFFFFFFFull;  // iou=0.0, j=0
        } else {
            int j = i - N;
            make_geom(gt + 8 * j, d_geomG[j]);
            Geom& g = d_geomG[j];
            d_ccG[j] = make_float4(g.cx, g.cy, g.rad, 0.f);
            float z = gt[8 * j + 2], dz = gt[8 * j + 5];
            d_gzmin[j] = z - dz * 0.5f;
            d_gzmax[j] = z + dz * 0.5f;
            d_gvol[j]  = gt[8 * j + 3] * gt[8 * j + 4] * dz;
        }
    }
}

__device__ __forceinline__ void queue_pair(bool pass, int* q, int* cnt,
                                           int i, int j, int lane) {
    unsigned bal = __ballot_sync(0xffffffffu, pass);
    if (bal) {
        int leader = __ffs(bal) - 1;
        int base = 0;
        if (lane == leader) base = atomicAdd(cnt, __popc(bal));
        base = __shfl_sync(0xffffffffu, base, leader);
        if (pass) {
            int ofs = __popc(bal & ((1u << lane) - 1u));
            q[base + ofs] = (i << 10) | j;
        }
    }
}

// blocks [0,1024): NMS circle test (order space, j>i), zero own maskT column.
// blocks [1024,2048): iou z-overlap + circle test (sampled filter deferred).
__global__ void pairgen_kernel() {
    int row = blockIdx.x;
    int t = threadIdx.x;
    int lane = t & 31;
    if (row < N) {
        int i = row;
        if (t < 32) d_maskT[i * 32 + t] = 0u;
        float4 ci = d_ccGo[i];
#pragma unroll
        for (int s = 0; s < 4; s++) {
            int j = t + 256 * s;
            bool pass = false;
            if (j > i) {
                float4 cj = d_ccGo[j];
                float dx = ci.x - cj.x, dy = ci.y - cj.y;
                float rr = ci.z + cj.z;
                pass = (dx * dx + dy * dy <= rr * rr);
            }
            queue_pair(pass, d_nms_pairs, &d_nms_cnt, i, j, lane);
        }
    } else {
        int i = row - N;
        float4 ci = d_ccP[i];
        float amin = d_pzmin[i], amax = d_pzmax[i];
#pragma unroll
        for (int s = 0; s < 4; s++) {
            int j = t + 256 * s;
            float oh = fminf(amax, d_gzmax[j]) - fmaxf(amin, d_gzmin[j]);
            bool pass = false;
            if (oh > 0.f) {
                float4 cj = d_ccG[j];
                float dx = ci.x - cj.x, dy = ci.y - cj.y;
                float rr = ci.z + cj.z;
                pass = (dx * dx + dy * dy <= rr * rr);
            }
            queue_pair(pass, d_iou_pairs, &d_iou_cnt, i, j, lane);
        }
    }
}

// full clip on survivors; record in-edge i -> j in transposed mask
__global__ void nms_process_kernel() {
    int cnt = d_nms_cnt;
    int stride = gridDim.x * blockDim.x;
    for (int idx = blockIdx.x * blockDim.x + threadIdx.x; idx < cnt; idx += stride) {
        int pr = d_nms_pairs[idx];
        int i = pr >> 10, j = pr & 1023;
        Geom A = d_geomGo[i];
        Geom B = d_geomGo[j];
        float inter = rect_inter_sh(A, B);
        float un = fmaxf(A.area + B.area - inter, EPSF);
        if (inter / un > 0.1f)
            atomicOr(&d_maskT[j * 32 + (i >> 5)], 1u << (i & 31));
    }
}

// synchronous fixpoint NMS: K_{t+1}[j] = !exists i<j kept with edge(i,j).
// Converges to the greedy NMS result in (max suppression-chain depth) iters.
__global__ void nms_fix_kernel() {
    __shared__ unsigned keepw[32];
    __shared__ int changed;
    int j = threadIdx.x;
    int w = j >> 5, lane = j & 31;
    unsigned col[32];
    bool any = false;
#pragma unroll
    for (int i = 0; i < 32; i++) {
        col[i] = d_maskT[j * 32 + i];
        any |= (col[i] != 0u);
    }
    bool kept = true;
    for (int it = 0; it < 1025; it++) {
        unsigned bw = __ballot_sync(0xffffffffu, kept);
        if (lane == 0) keepw[w] = bw;
        if (j == 0) changed = 0;
        __syncthreads();
        bool newkept = true;
        if (any) {
            unsigned acc = 0u;
#pragma unroll
            for (int i = 0; i < 32; i++)
                if (col[i]) acc |= (col[i] & keepw[i]);
            newkept = (acc == 0u);
        }
        if (newkept != kept) changed = 1;
        __syncthreads();
        kept = newkept;
        if (!changed) break;
    }
    d_sampled[d_order[j]] = kept ? 1 : 0;
}

// key = (iou_bits << 32) | (0xFFFFFFFF - j) -> max iou, ties -> smallest j
__global__ void iou_process_kernel() {
    int cnt = d_iou_cnt;
    int stride = gridDim.x * blockDim.x;
    for (int idx = blockIdx.x * blockDim.x + threadIdx.x; idx < cnt; idx += stride) {
        int pr = d_iou_pairs[idx];
        int i = pr >> 10, j = pr & 1023;
        if (!d_sampled[j]) continue;
        Geom A = d_geomP[i];
        Geom B = d_geomG[j];
        float oh = fminf(d_pzmax[i], d_gzmax[j]) - fmaxf(d_pzmin[i], d_gzmin[j]);
        float inter = rect_inter_sh(A, B) * oh;
        float un = fmaxf(d_pvol[i] + d_gvol[j] - inter, EPSF);
        float iou = inter / un;
        if (iou > 0.f) {
            unsigned long long key =
                (((unsigned long long)__float_as_uint(iou)) << 32) |
                (unsigned long long)(0xFFFFFFFFu - (unsigned)j);
            atomicMax(&d_best[i], key);
        }
    }
}

__global__ void finalize_kernel(const float* __restrict__ labels,
                                const float* __restrict__ cls,
                                float* __restrict__ out) {
    int i = blockIdx.x * blockDim.x + threadIdx.x;
    if (i >= N) return;
    float cp = 1.f / (1.f + expf(-cls[i]));
    out[i]     = (cp > 0.55f && labels[i] > 0.55f) ? 1.0f : 0.0f;
    out[N + i] = labels[i];
    unsigned long long key = d_best[i];
    float mo = __uint_as_float((unsigned)(key >> 32));
    int j = (int)(0xFFFFFFFFu - (unsigned)(key & 0xFFFFFFFFull));
    mo = (mo > 0.75f) ? 1.0f : ((mo < 0.25f) ? 0.0f : mo);
    out[2 * N + i] = mo;
    out[3 * N + i] = (float)j;
}

extern "C" void kernel_launch(void* const* d_in, const int* in_sizes, int n_in,
                              void* d_out, int out_size) {
    const float* labels = (const float*)d_in[0];
    const float* pred   = (const float*)d_in[1];
    const float* gt     = (const float*)d_in[2];
    const float* cls    = (const float*)d_in[3];
    if (n_in >= 3 && in_sizes[1] == 8 * N && in_sizes[2] == 7 * N) {
        pred = (const float*)d_in[2];
        gt   = (const float*)d_in[1];
    }
    float* out = (float*)d_out;

    prep_rank_kernel<<<N + 8, 256>>>(pred, gt, labels);
    pairgen_kernel<<<2 * N, 256>>>();
    nms_process_kernel<<<256, 256>>>();
    nms_fix_kernel<<<1, 1024>>>();
    iou_process_kernel<<<256, 256>>>();
    finalize_kernel<<<(N + 255) / 256, 256>>>(labels, cls, out);
}

// round 6
// speedup vs baseline: 4.8101x; 1.0319x over previous
#include <cuda_runtime.h>
#include <math.h>

#define N 1024
#define EPSF 1e-8f

struct __align__(16) Geom {
    float cx, cy, cs, sn, hx, hy, rad, area;
    float x[4], y[4];
};

__device__ Geom d_geomP[N];
__device__ Geom d_geomG[N];
__device__ Geom d_geomGo[N];
__device__ float4 d_ccP[N];
__device__ float4 d_ccG[N];
__device__ float4 d_ccGo[N];
__device__ int d_order[N];
__device__ unsigned int d_maskW[32 * N];  // [w][j]: in-edges to col j from word w (cross-word, i<j)
__device__ unsigned int d_inword[32 * 32]; // [w][b]: out-edges of i=32w+b to j within word w
__device__ int d_sampled[N];
__device__ float d_pzmin[N], d_pzmax[N], d_pvol[N];
__device__ float d_gzmin[N], d_gzmax[N], d_gvol[N];
__device__ unsigned long long d_best[N];
__device__ int d_nms_cnt;
__device__ int d_iou_cnt;
__device__ int d_nms_pairs[N * N / 2];
__device__ int d_iou_pairs[N * N];

__device__ __forceinline__ void make_geom(const float* b, Geom& g) {
    float cx = b[0], cy = b[1], dx = b[3], dy = b[4], r = b[6];
    float sn, cs;
    sincosf(r, &sn, &cs);
    float hx = 0.5f * dx, hy = 0.5f * dy;
    g.cx = cx; g.cy = cy; g.cs = cs; g.sn = sn;
    g.hx = hx; g.hy = hy;
    g.rad = 0.5f * sqrtf(dx * dx + dy * dy);
    g.area = dx * dy;
    g.x[0] =  hx * cs - hy * sn + cx;  g.y[0] =  hx * sn + hy * cs + cy;
    g.x[1] =  hx * cs + hy * sn + cx;  g.y[1] =  hx * sn - hy * cs + cy;
    g.x[2] = -hx * cs + hy * sn + cx;  g.y[2] = -hx * sn - hy * cs + cy;
    g.x[3] = -hx * cs - hy * sn * 0.f - hy * sn + cx;  g.y[3] = -hx * sn + hy * cs + cy;
}

// Sutherland–Hodgman clip of B by A's 4 half-planes (CW rect, interior <= 0).
__device__ float rect_inter_sh(const Geom& A, const Geom& B) {
    float qx[8], qy[8];
    int n = 4;
#pragma unroll
    for (int c = 0; c < 4; c++) { qx[c] = B.x[c]; qy[c] = B.y[c]; }
#pragma unroll
    for (int e = 0; e < 4; e++) {
        float x0 = A.x[e], y0 = A.y[e];
        float ex = A.x[(e + 1) & 3] - x0, ey = A.y[(e + 1) & 3] - y0;
        float rx[8], ry[8];
        int m = 0;
        float sxp = qx[n - 1], syp = qy[n - 1];
        float dp = ex * (syp - y0) - ey * (sxp - x0);
        for (int v = 0; v < n; v++) {
            float cxv = qx[v], cyv = qy[v];
            float dc = ex * (cyv - y0) - ey * (cxv - x0);
            bool inp = dp <= 0.f, inc = dc <= 0.f;
            if (inp != inc) {
                float t = dp / (dp - dc);
                rx[m] = sxp + t * (cxv - sxp);
                ry[m] = syp + t * (cyv - syp);
                m++;
            }
            if (inc) { rx[m] = cxv; ry[m] = cyv; m++; }
            sxp = cxv; syp = cyv; dp = dc;
        }
        n = m;
        if (n == 0) return 0.f;
        for (int v = 0; v < n; v++) { qx[v] = rx[v]; qy[v] = ry[v]; }
    }
    float s2 = 0.f;
    for (int v = 0; v < n; v++) {
        int w = (v + 1 < n) ? (v + 1) : 0;
        s2 += qx[v] * qy[w] - qy[v] * qx[w];
    }
    return 0.5f * fabsf(s2);
}

// ---------------- kernels ----------------

__global__ void prep_rank_kernel(const float* __restrict__ pred,
                                 const float* __restrict__ gt,
                                 const float* __restrict__ scores) {
    int b = blockIdx.x;
    int t = threadIdx.x;
    if (b < N) {
        __shared__ int cnt;
        if (t == 0) cnt = 0;
        __syncthreads();
        float si = scores[b];
        int c = 0;
#pragma unroll
        for (int s = 0; s < 4; s++) {
            int j = t + 256 * s;
            float sj = scores[j];
            c += (sj > si) || (sj == si && j < b);
        }
        c += __shfl_down_sync(0xffffffffu, c, 16);
        c += __shfl_down_sync(0xffffffffu, c, 8);
        c += __shfl_down_sync(0xffffffffu, c, 4);
        c += __shfl_down_sync(0xffffffffu, c, 2);
        c += __shfl_down_sync(0xffffffffu, c, 1);
        if ((t & 31) == 0) atomicAdd(&cnt, c);
        __syncthreads();
        if (t == 0) {
            int r = cnt;
            d_order[r] = b;
            Geom g;
            make_geom(gt + 8 * b, g);
            d_geomGo[r] = g;
            d_ccGo[r] = make_float4(g.cx, g.cy, g.rad, 0.f);
        }
    } else {
        int i = (b - N) * 256 + t;  // 0..2047
        if (b == N && t == 0) { d_nms_cnt = 0; d_iou_cnt = 0; }
        if (i < N) {
            d_inword[i & 1023] = 0u;  // 1024 words zeroed by the pred-prep threads
            make_geom(pred + 7 * i, d_geomP[i]);
            Geom& g = d_geomP[i];
            d_ccP[i] = make_float4(g.cx, g.cy, g.rad, 0.f);
            float z = pred[7 * i + 2], dz = pred[7 * i + 5];
            d_pzmin[i] = z - dz * 0.5f;
            d_pzmax[i] = z + dz * 0.5f;
            d_pvol[i]  = pred[7 * i + 3] * pred[7 * i + 4] * dz;
            d_best[i] = 0xFFFFFFFFull;  // iou=0.0, j=0
        } else {
            int j = i - N;
            make_geom(gt + 8 * j, d_geomG[j]);
            Geom& g = d_geomG[j];
            d_ccG[j] = make_float4(g.cx, g.cy, g.rad, 0.f);
            float z = gt[8 * j + 2], dz = gt[8 * j + 5];
            d_gzmin[j] = z - dz * 0.5f;
            d_gzmax[j] = z + dz * 0.5f;
            d_gvol[j]  = gt[8 * j + 3] * gt[8 * j + 4] * dz;
        }
    }
}

__device__ __forceinline__ void queue_pair(bool pass, int* q, int* cnt,
                                           int i, int j, int lane) {
    unsigned bal = __ballot_sync(0xffffffffu, pass);
    if (bal) {
        int leader = __ffs(bal) - 1;
        int base = 0;
        if (lane == leader) base = atomicAdd(cnt, __popc(bal));
        base = __shfl_sync(0xffffffffu, base, leader);
        if (pass) {
            int ofs = __popc(bal & ((1u << lane) - 1u));
            q[base + ofs] = (i << 10) | j;
        }
    }
}

// blocks [0,1024): NMS circle test (order space, j>i), zero own maskW column.
// blocks [1024,2048): iou z-overlap + circle test (sampled filter deferred).
__global__ void pairgen_kernel() {
    int row = blockIdx.x;
    int t = threadIdx.x;
    int lane = t & 31;
    if (row < N) {
        int i = row;
        if (t < 32) d_maskW[t * N + i] = 0u;
        float4 ci = d_ccGo[i];
#pragma unroll
        for (int s = 0; s < 4; s++) {
            int j = t + 256 * s;
            bool pass = false;
            if (j > i) {
                float4 cj = d_ccGo[j];
                float dx = ci.x - cj.x, dy = ci.y - cj.y;
                float rr = ci.z + cj.z;
                pass = (dx * dx + dy * dy <= rr * rr);
            }
            queue_pair(pass, d_nms_pairs, &d_nms_cnt, i, j, lane);
        }
    } else {
        int i = row - N;
        float4 ci = d_ccP[i];
        float amin = d_pzmin[i], amax = d_pzmax[i];
#pragma unroll
        for (int s = 0; s < 4; s++) {
            int j = t + 256 * s;
            float oh = fminf(amax, d_gzmax[j]) - fmaxf(amin, d_gzmin[j]);
            bool pass = false;
            if (oh > 0.f) {
                float4 cj = d_ccG[j];
                float dx = ci.x - cj.x, dy = ci.y - cj.y;
                float rr = ci.z + cj.z;
                pass = (dx * dx + dy * dy <= rr * rr);
            }
            queue_pair(pass, d_iou_pairs, &d_iou_cnt, i, j, lane);
        }
    }
}

// full clip on survivors; record edge i -> j (i<j) in word-major / in-word maps
__global__ void nms_process_kernel() {
    int cnt = d_nms_cnt;
    int stride = gridDim.x * blockDim.x;
    for (int idx = blockIdx.x * blockDim.x + threadIdx.x; idx < cnt; idx += stride) {
        int pr = d_nms_pairs[idx];
        int i = pr >> 10, j = pr & 1023;
        Geom A = d_geomGo[i];
        Geom B = d_geomGo[j];
        float inter = rect_inter_sh(A, B);
        float un = fmaxf(A.area + B.area - inter, EPSF);
        if (inter / un > 0.1f) {
            int wi = i >> 5;
            if (wi == (j >> 5))
                atomicOr(&d_inword[wi * 32 + (i & 31)], 1u << (j & 31));
            else
                atomicOr(&d_maskW[wi * N + j], 1u << (i & 31));
        }
    }
}

// exact greedy NMS via word-level Gauss-Seidel: 32 deterministic steps.
__global__ void __launch_bounds__(1024, 1) nms_gs_kernel() {
    int j = threadIdx.x;
    int w = j >> 5, lane = j & 31;
    __shared__ unsigned keepw[32];
    unsigned rows[32];
    if (lane == 0) {
#pragma unroll
        for (int b = 0; b < 32; b++) rows[b] = d_inword[w * 32 + b];
    }
    bool sup = false;
#pragma unroll
    for (int w2 = 0; w2 < 32; w2++) {
        unsigned colw = d_maskW[w2 * N + j];  // prefetch this step's in-edge word
        if (w == w2) {
            unsigned cur_sup = __ballot_sync(0xffffffffu, sup);
            if (lane == 0) {
                unsigned kept = 0u, alive = ~cur_sup;
#pragma unroll
                for (int b = 0; b < 32; b++) {
                    unsigned bit = 1u << b;
                    if (alive & bit) { kept |= bit; alive &= ~rows[b]; }
                }
                keepw[w2] = kept;
            }
        }
        __syncthreads();
        sup = sup || ((colw & keepw[w2]) != 0u);
    }
    d_sampled[d_order[j]] = (keepw[w] >> lane) & 1u;
}

// key = (iou_bits << 32) | (0xFFFFFFFF - j) -> max iou, ties -> smallest j
__global__ void iou_process_kernel() {
    int cnt = d_iou_cnt;
    int stride = gridDim.x * blockDim.x;
    for (int idx = blockIdx.x * blockDim.x + threadIdx.x; idx < cnt; idx += stride) {
        int pr = d_iou_pairs[idx];
        int i = pr >> 10, j = pr & 1023;
        if (!d_sampled[j]) continue;
        Geom A = d_geomP[i];
        Geom B = d_geomG[j];
        float oh = fminf(d_pzmax[i], d_gzmax[j]) - fmaxf(d_pzmin[i], d_gzmin[j]);
        float inter = rect_inter_sh(A, B) * oh;
        float un = fmaxf(d_pvol[i] + d_gvol[j] - inter, EPSF);
        float iou = inter / un;
        if (iou > 0.f) {
            unsigned long long key =
                (((unsigned long long)__float_as_uint(iou)) << 32) |
                (unsigned long long)(0xFFFFFFFFu - (unsigned)j);
            atomicMax(&d_best[i], key);
        }
    }
}

__global__ void finalize_kernel(const float* __restrict__ labels,
                                const float* __restrict__ cls,
                                float* __restrict__ out) {
    int i = blockIdx.x * blockDim.x + threadIdx.x;
    if (i >= N) return;
    float cp = 1.f / (1.f + expf(-cls[i]));
    out[i]     = (cp > 0.55f && labels[i] > 0.55f) ? 1.0f : 0.0f;
    out[N + i] = labels[i];
    unsigned long long key = d_best[i];
    float mo = __uint_as_float((unsigned)(key >> 32));
    int j = (int)(0xFFFFFFFFu - (unsigned)(key & 0xFFFFFFFFull));
    mo = (mo > 0.75f) ? 1.0f : ((mo < 0.25f) ? 0.0f : mo);
    out[2 * N + i] = mo;
    out[3 * N + i] = (float)j;
}

extern "C" void kernel_launch(void* const* d_in, const int* in_sizes, int n_in,
                              void* d_out, int out_size) {
    const float* labels = (const float*)d_in[0];
    const float* pred   = (const float*)d_in[1];
    const float* gt     = (const float*)d_in[2];
    const float* cls    = (const float*)d_in[3];
    if (n_in >= 3 && in_sizes[1] == 8 * N && in_sizes[2] == 7 * N) {
        pred = (const float*)d_in[2];
        gt   = (const float*)d_in[1];
    }
    float* out = (float*)d_out;

    prep_rank_kernel<<<N + 8, 256>>>(pred, gt, labels);
    pairgen_kernel<<<2 * N, 256>>>();
    nms_process_kernel<<<256, 256>>>();
    nms_gs_kernel<<<1, 1024>>>();
    iou_process_kernel<<<256, 256>>>();
    finalize_kernel<<<(N + 255) / 256, 256>>>(labels, cls, out);
}

// round 9
// speedup vs baseline: 5.9958x; 1.2465x over previous
#include <cuda_runtime.h>
#include <math.h>

#define N 1024
#define EPSF 1e-8f

struct __align__(16) Geom {
    float cx, cy, cs, sn, hx, hy, rad, area;
    float x[4], y[4];
};

__device__ Geom d_geomP[N];
__device__ Geom d_geomG[N];
__device__ Geom d_geomGo[N];
__device__ float4 d_ccP[N];
__device__ float4 d_ccG[N];
__device__ float4 d_ccGo[N];
__device__ int d_order[N];
__device__ unsigned int d_maskW[32 * N];   // [w][j]: in-edges to col j from word w (cross-word, i<j)
__device__ unsigned int d_inword[32 * 32]; // [w][b]: out-edges of i=32w+b to j within word w
__device__ int d_sampled[N];
__device__ float d_pzmin[N], d_pzmax[N], d_pvol[N];
__device__ float d_gzmin[N], d_gzmax[N], d_gvol[N];
__device__ unsigned long long d_best[N];

__device__ __forceinline__ void make_geom(const float* b, Geom& g) {
    float cx = b[0], cy = b[1], dx = b[3], dy = b[4], r = b[6];
    float sn, cs;
    sincosf(r, &sn, &cs);
    float hx = 0.5f * dx, hy = 0.5f * dy;
    g.cx = cx; g.cy = cy; g.cs = cs; g.sn = sn;
    g.hx = hx; g.hy = hy;
    g.rad = 0.5f * sqrtf(dx * dx + dy * dy);
    g.area = dx * dy;
    g.x[0] =  hx * cs - hy * sn + cx;  g.y[0] =  hx * sn + hy * cs + cy;
    g.x[1] =  hx * cs + hy * sn + cx;  g.y[1] =  hx * sn - hy * cs + cy;
    g.x[2] = -hx * cs + hy * sn + cx;  g.y[2] = -hx * sn - hy * cs + cy;
    g.x[3] = -hx * cs - hy * sn + cx;  g.y[3] = -hx * sn + hy * cs + cy;
}

// Sutherland–Hodgman clip of B by A's 4 half-planes (CW rect, interior <= 0).
__device__ float rect_inter_sh(const Geom& A, const Geom& B) {
    float qx[8], qy[8];
    int n = 4;
#pragma unroll
    for (int c = 0; c < 4; c++) { qx[c] = B.x[c]; qy[c] = B.y[c]; }
#pragma unroll
    for (int e = 0; e < 4; e++) {
        float x0 = A.x[e], y0 = A.y[e];
        float ex = A.x[(e + 1) & 3] - x0, ey = A.y[(e + 1) & 3] - y0;
        float rx[8], ry[8];
        int m = 0;
        float sxp = qx[n - 1], syp = qy[n - 1];
        float dp = ex * (syp - y0) - ey * (sxp - x0);
        for (int v = 0; v < n; v++) {
            float cxv = qx[v], cyv = qy[v];
            float dc = ex * (cyv - y0) - ey * (cxv - x0);
            bool inp = dp <= 0.f, inc = dc <= 0.f;
            if (inp != inc) {
                float t = dp / (dp - dc);
                rx[m] = sxp + t * (cxv - sxp);
                ry[m] = syp + t * (cyv - syp);
                m++;
            }
            if (inc) { rx[m] = cxv; ry[m] = cyv; m++; }
            sxp = cxv; syp = cyv; dp = dc;
        }
        n = m;
        if (n == 0) return 0.f;
        for (int v = 0; v < n; v++) { qx[v] = rx[v]; qy[v] = ry[v]; }
    }
    float s2 = 0.f;
    for (int v = 0; v < n; v++) {
        int w = (v + 1 < n) ? (v + 1) : 0;
        s2 += qx[v] * qy[w] - qy[v] * qx[w];
    }
    return 0.5f * fabsf(s2);
}

// ---------------- kernels ----------------

// blocks [0,N): stable descending rank of gt box b + order-space geom write.
// blocks [N,N+8): per-box prep (pred then gt) + zero maskW/inword.
__global__ void prep_rank_kernel(const float* __restrict__ pred,
                                 const float* __restrict__ gt,
                                 const float* __restrict__ scores) {
    int b = blockIdx.x;
    int t = threadIdx.x;
    if (b < N) {
        __shared__ int cnt;
        if (t == 0) cnt = 0;
        __syncthreads();
        float si = scores[b];
        int c = 0;
#pragma unroll
        for (int s = 0; s < 4; s++) {
            int j = t + 256 * s;
            float sj = scores[j];
            c += (sj > si) || (sj == si && j < b);
        }
        c += __shfl_down_sync(0xffffffffu, c, 16);
        c += __shfl_down_sync(0xffffffffu, c, 8);
        c += __shfl_down_sync(0xffffffffu, c, 4);
        c += __shfl_down_sync(0xffffffffu, c, 2);
        c += __shfl_down_sync(0xffffffffu, c, 1);
        if ((t & 31) == 0) atomicAdd(&cnt, c);
        __syncthreads();
        if (t == 0) {
            int r = cnt;
            d_order[r] = b;
            Geom g;
            make_geom(gt + 8 * b, g);
            d_geomGo[r] = g;
            d_ccGo[r] = make_float4(g.cx, g.cy, g.rad, 0.f);
        }
    } else {
        int i = (b - N) * 256 + t;  // 0..2047
#pragma unroll
        for (int k = 0; k < 16; k++)          // zero 32K-word maskW
            d_maskW[i + 2048 * k] = 0u;
        if (i < N) {
            d_inword[i] = 0u;
            make_geom(pred + 7 * i, d_geomP[i]);
            Geom& g = d_geomP[i];
            d_ccP[i] = make_float4(g.cx, g.cy, g.rad, 0.f);
            float z = pred[7 * i + 2], dz = pred[7 * i + 5];
            d_pzmin[i] = z - dz * 0.5f;
            d_pzmax[i] = z + dz * 0.5f;
            d_pvol[i]  = pred[7 * i + 3] * pred[7 * i + 4] * dz;
        } else {
            int j = i - N;
            make_geom(gt + 8 * j, d_geomG[j]);
            Geom& g = d_geomG[j];
            d_ccG[j] = make_float4(g.cx, g.cy, g.rad, 0.f);
            float z = gt[8 * j + 2], dz = gt[8 * j + 5];
            d_gzmin[j] = z - dz * 0.5f;
            d_gzmax[j] = z + dz * 0.5f;
            d_gvol[j]  = gt[8 * j + 3] * gt[8 * j + 4] * dz;
        }
    }
}

// fused NMS row: circle test -> smem list -> converged clip -> edge bits
__global__ void nms_fused_kernel() {
    __shared__ int s_pairs[1024];
    __shared__ int s_cnt;
    int i = blockIdx.x, t = threadIdx.x;
    if (t == 0) s_cnt = 0;
    __syncthreads();
    float4 ci = d_ccGo[i];
#pragma unroll
    for (int s = 0; s < 4; s++) {
        int j = t + 256 * s;
        if (j > i) {
            float4 cj = d_ccGo[j];
            float dx = ci.x - cj.x, dy = ci.y - cj.y;
            float rr = ci.z + cj.z;
            if (dx * dx + dy * dy <= rr * rr)
                s_pairs[atomicAdd(&s_cnt, 1)] = j;
        }
    }
    __syncthreads();
    int cnt = s_cnt;
    if (cnt == 0) return;
    Geom A = d_geomGo[i];
    for (int p = t; p < cnt; p += 256) {
        int j = s_pairs[p];
        Geom B = d_geomGo[j];
        float inter = rect_inter_sh(A, B);
        float un = fmaxf(A.area + B.area - inter, EPSF);
        if (inter / un > 0.1f) {
            int wi = i >> 5;
            if (wi == (j >> 5))
                atomicOr(&d_inword[wi * 32 + (i & 31)], 1u << (j & 31));
            else
                atomicOr(&d_maskW[wi * N + j], 1u << (i & 31));
        }
    }
}

// exact greedy NMS via word-level Gauss-Seidel: 32 deterministic steps.
// Outer loop NOT unrolled (code must fit L0 I$); inner resolve unrolled.
__global__ void __launch_bounds__(1024, 1) nms_gs_kernel() {
    int j = threadIdx.x;
    int w = j >> 5, lane = j & 31;
    __shared__ unsigned keepw[32];
    unsigned rows[32];
    if (lane == 0) {
#pragma unroll
        for (int b = 0; b < 32; b++) rows[b] = d_inword[w * 32 + b];
    }
    bool sup = false;
    const unsigned* colp = d_maskW + j;
#pragma unroll 1
    for (int w2 = 0; w2 < 32; w2++) {
        unsigned colw = colp[w2 * N];
        if (w == w2) {
            unsigned cur_sup = __ballot_sync(0xffffffffu, sup);
            if (lane == 0) {
                unsigned kept = 0u, alive = ~cur_sup;
#pragma unroll
                for (int b = 0; b < 32; b++) {
                    unsigned bit = 1u << b;
                    if (alive & bit) { kept |= bit; alive &= ~rows[b]; }
                }
                keepw[w2] = kept;
            }
        }
        __syncthreads();
        sup = sup || ((colw & keepw[w2]) != 0u);
    }
    d_sampled[d_order[j]] = (keepw[w] >> lane) & 1u;
}

// fused iou3d row: filter -> smem list -> converged clip -> block argmax ->
// write all four outputs for pred i (finalize absorbed).
__global__ void iou_fused_kernel(const float* __restrict__ labels,
                                 const float* __restrict__ cls,
                                 float* __restrict__ out) {
    __shared__ int s_pairs[1024];
    __shared__ int s_cnt;
    __shared__ unsigned long long s_best;
    int i = blockIdx.x, t = threadIdx.x;
    if (t == 0) { s_cnt = 0; s_best = 0xFFFFFFFFull; }  // iou=0.0, j=0
    __syncthreads();
    float4 ci = d_ccP[i];
    float amin = d_pzmin[i], amax = d_pzmax[i];
#pragma unroll
    for (int s = 0; s < 4; s++) {
        int j = t + 256 * s;
        if (d_sampled[j]) {
            float oh = fminf(amax, d_gzmax[j]) - fmaxf(amin, d_gzmin[j]);
            if (oh > 0.f) {
                float4 cj = d_ccG[j];
                float dx = ci.x - cj.x, dy = ci.y - cj.y;
                float rr = ci.z + cj.z;
                if (dx * dx + dy * dy <= rr * rr)
                    s_pairs[atomicAdd(&s_cnt, 1)] = j;
            }
        }
    }
    __syncthreads();
    int cnt = s_cnt;
    if (cnt > 0) {
        Geom A = d_geomP[i];
        float va = d_pvol[i];
        for (int p = t; p < cnt; p += 256) {
            int j = s_pairs[p];
            Geom B = d_geomG[j];
            float oh = fminf(amax, d_gzmax[j]) - fmaxf(amin, d_gzmin[j]);
            float inter = rect_inter_sh(A, B) * oh;
            float un = fmaxf(va + d_gvol[j] - inter, EPSF);
            float iou = inter / un;
            if (iou > 0.f) {
                unsigned long long key =
                    (((unsigned long long)__float_as_uint(iou)) << 32) |
                    (unsigned long long)(0xFFFFFFFFu - (unsigned)j);
                atomicMax(&s_best, key);
            }
        }
    }
    __syncthreads();
    if (t == 0) {
        unsigned long long key = s_best;
        float mo = __uint_as_float((unsigned)(key >> 32));
        int jb = (int)(0xFFFFFFFFu - (unsigned)(key & 0xFFFFFFFFull));
        mo = (mo > 0.75f) ? 1.0f : ((mo < 0.25f) ? 0.0f : mo);
        float lab = labels[i];
        float cp = 1.f / (1.f + expf(-cls[i]));
        out[i]         = (cp > 0.55f && lab > 0.55f) ? 1.0f : 0.0f;
        out[N + i]     = lab;
        out[2 * N + i] = mo;
        out[3 * N + i] = (float)jb;
    }
}

extern "C" void kernel_launch(void* const* d_in, const int* in_sizes, int n_in,
                              void* d_out, int out_size) {
    const float* labels = (const float*)d_in[0];
    const float* pred   = (const float*)d_in[1];
    const float* gt     = (const float*)d_in[2];
    const float* cls    = (const float*)d_in[3];
    if (n_in >= 3 && in_sizes[1] == 8 * N && in_sizes[2] == 7 * N) {
        pred = (const float*)d_in[2];
        gt   = (const float*)d_in[1];
    }
    float* out = (float*)d_out;

    prep_rank_kernel<<<N + 8, 256>>>(pred, gt, labels);
    nms_fused_kernel<<<N, 256>>>();
    nms_gs_kernel<<<1, 1024>>>();
    iou_fused_kernel<<<N, 256>>>(labels, cls, out);
}

// round 11
// speedup vs baseline: 6.3132x; 1.0529x over previous
#include <cuda_runtime.h>
#include <math.h>

#define N 1024
#define EPSF 1e-8f

struct __align__(16) Geom {
    float cx, cy, cs, sn, hx, hy, rad, area;
    float x[4], y[4];
};

__device__ Geom d_geomP[N];
__device__ Geom d_geomG[N];
__device__ Geom d_geomGo[N];
__device__ float4 d_ccP[N];
__device__ float4 d_ccG[N];
__device__ float4 d_ccGo[N];
__device__ int d_order[N];
__device__ unsigned int d_maskW[32 * N];   // [w][j]: in-edges to col j from word w (cross-word, i<j)
__device__ unsigned int d_inword[32 * 32]; // [w][b]: out-edges of i=32w+b to j within word w
__device__ float d_pzmin[N], d_pzmax[N], d_pvol[N];
__device__ float d_gzmin[N], d_gzmax[N], d_gvol[N];
// compact kept-gt arrays (written by nms_gs)
__device__ Geom d_geomK[N];
__device__ float4 d_ccK[N];   // cx, cy, rad, vol
__device__ float2 d_zK[N];    // zmin, zmax
__device__ int d_joK[N];      // original gt index
__device__ int d_Scnt;

__device__ __forceinline__ void make_geom(const float* b, Geom& g) {
    float cx = b[0], cy = b[1], dx = b[3], dy = b[4], r = b[6];
    float sn, cs;
    sincosf(r, &sn, &cs);
    float hx = 0.5f * dx, hy = 0.5f * dy;
    g.cx = cx; g.cy = cy; g.cs = cs; g.sn = sn;
    g.hx = hx; g.hy = hy;
    g.rad = 0.5f * sqrtf(dx * dx + dy * dy);
    g.area = dx * dy;
    g.x[0] =  hx * cs - hy * sn + cx;  g.y[0] =  hx * sn + hy * cs + cy;
    g.x[1] =  hx * cs + hy * sn + cx;  g.y[1] =  hx * sn - hy * cs + cy;
    g.x[2] = -hx * cs + hy * sn + cx;  g.y[2] = -hx * sn - hy * cs + cy;
    g.x[3] = -hx * cs - hy * sn + cx;  g.y[3] = -hx * sn + hy * cs + cy;
}

// Sutherland–Hodgman clip of B by A's 4 half-planes (CW rect, interior <= 0).
__device__ float rect_inter_sh(const Geom& A, const Geom& B) {
    float qx[8], qy[8];
    int n = 4;
#pragma unroll
    for (int c = 0; c < 4; c++) { qx[c] = B.x[c]; qy[c] = B.y[c]; }
#pragma unroll
    for (int e = 0; e < 4; e++) {
        float x0 = A.x[e], y0 = A.y[e];
        float ex = A.x[(e + 1) & 3] - x0, ey = A.y[(e + 1) & 3] - y0;
        float rx[8], ry[8];
        int m = 0;
        float sxp = qx[n - 1], syp = qy[n - 1];
        float dp = ex * (syp - y0) - ey * (sxp - x0);
        for (int v = 0; v < n; v++) {
            float cxv = qx[v], cyv = qy[v];
            float dc = ex * (cyv - y0) - ey * (cxv - x0);
            bool inp = dp <= 0.f, inc = dc <= 0.f;
            if (inp != inc) {
                float t = dp / (dp - dc);
                rx[m] = sxp + t * (cxv - sxp);
                ry[m] = syp + t * (cyv - syp);
                m++;
            }
            if (inc) { rx[m] = cxv; ry[m] = cyv; m++; }
            sxp = cxv; syp = cyv; dp = dc;
        }
        n = m;
        if (n == 0) return 0.f;
        for (int v = 0; v < n; v++) { qx[v] = rx[v]; qy[v] = ry[v]; }
    }
    float s2 = 0.f;
    for (int v = 0; v < n; v++) {
        int w = (v + 1 < n) ? (v + 1) : 0;
        s2 += qx[v] * qy[w] - qy[v] * qx[w];
    }
    return 0.5f * fabsf(s2);
}

// ---------------- kernels ----------------

// blocks [0,N): stable descending rank of gt box b + order-space geom write.
// blocks [N,N+8): per-box prep (pred then gt) + zero maskW/inword.
__global__ void prep_rank_kernel(const float* __restrict__ pred,
                                 const float* __restrict__ gt,
                                 const float* __restrict__ scores) {
    int b = blockIdx.x;
    int t = threadIdx.x;
    if (b < N) {
        __shared__ int cnt;
        if (t == 0) cnt = 0;
        __syncthreads();
        float si = scores[b];
        int c = 0;
#pragma unroll
        for (int s = 0; s < 4; s++) {
            int j = t + 256 * s;
            float sj = scores[j];
            c += (sj > si) || (sj == si && j < b);
        }
        c += __shfl_down_sync(0xffffffffu, c, 16);
        c += __shfl_down_sync(0xffffffffu, c, 8);
        c += __shfl_down_sync(0xffffffffu, c, 4);
        c += __shfl_down_sync(0xffffffffu, c, 2);
        c += __shfl_down_sync(0xffffffffu, c, 1);
        if ((t & 31) == 0) atomicAdd(&cnt, c);
        __syncthreads();
        if (t == 0) {
            int r = cnt;
            d_order[r] = b;
            Geom g;
            make_geom(gt + 8 * b, g);
            d_geomGo[r] = g;
            d_ccGo[r] = make_float4(g.cx, g.cy, g.rad, 0.f);
        }
    } else {
        int i = (b - N) * 256 + t;  // 0..2047
#pragma unroll
        for (int k = 0; k < 16; k++)          // zero 32K-word maskW
            d_maskW[i + 2048 * k] = 0u;
        if (i < N) {
            d_inword[i] = 0u;
            make_geom(pred + 7 * i, d_geomP[i]);
            Geom& g = d_geomP[i];
            d_ccP[i] = make_float4(g.cx, g.cy, g.rad, 0.f);
            float z = pred[7 * i + 2], dz = pred[7 * i + 5];
            d_pzmin[i] = z - dz * 0.5f;
            d_pzmax[i] = z + dz * 0.5f;
            d_pvol[i]  = pred[7 * i + 3] * pred[7 * i + 4] * dz;
        } else {
            int j = i - N;
            make_geom(gt + 8 * j, d_geomG[j]);
            Geom& g = d_geomG[j];
            d_ccG[j] = make_float4(g.cx, g.cy, g.rad, 0.f);
            float z = gt[8 * j + 2], dz = gt[8 * j + 5];
            d_gzmin[j] = z - dz * 0.5f;
            d_gzmax[j] = z + dz * 0.5f;
            d_gvol[j]  = gt[8 * j + 3] * gt[8 * j + 4] * dz;
        }
    }
}

// fused NMS row: circle test -> smem list -> converged clip -> edge bits
__global__ void nms_fused_kernel() {
    __shared__ int s_pairs[1024];
    __shared__ int s_cnt;
    int i = blockIdx.x, t = threadIdx.x;
    if (t == 0) s_cnt = 0;
    __syncthreads();
    float4 ci = d_ccGo[i];
#pragma unroll
    for (int s = 0; s < 4; s++) {
        int j = t + 256 * s;
        if (j > i) {
            float4 cj = d_ccGo[j];
            float dx = ci.x - cj.x, dy = ci.y - cj.y;
            float rr = ci.z + cj.z;
            if (dx * dx + dy * dy <= rr * rr)
                s_pairs[atomicAdd(&s_cnt, 1)] = j;
        }
    }
    __syncthreads();
    int cnt = s_cnt;
    if (cnt == 0) return;
    Geom A = d_geomGo[i];
    for (int p = t; p < cnt; p += 256) {
        int j = s_pairs[p];
        Geom B = d_geomGo[j];
        float inter = rect_inter_sh(A, B);
        float un = fmaxf(A.area + B.area - inter, EPSF);
        if (inter / un > 0.1f) {
            int wi = i >> 5;
            if (wi == (j >> 5))
                atomicOr(&d_inword[wi * 32 + (i & 31)], 1u << (j & 31));
            else
                atomicOr(&d_maskW[wi * N + j], 1u << (i & 31));
        }
    }
}

// exact greedy NMS (32-step word Gauss-Seidel) + compaction of kept gt.
__global__ void __launch_bounds__(1024, 1) nms_gs_kernel() {
    int j = threadIdx.x;
    int w = j >> 5, lane = j & 31;
    __shared__ unsigned keepw[32];
    __shared__ int warpoff[32];
    unsigned rows[32];
    if (lane == 0) {
#pragma unroll
        for (int b = 0; b < 32; b++) rows[b] = d_inword[w * 32 + b];
    }
    bool sup = false;
    const unsigned* colp = d_maskW + j;
#pragma unroll 1
    for (int w2 = 0; w2 < 32; w2++) {
        unsigned colw = colp[w2 * N];
        if (w == w2) {
            unsigned cur_sup = __ballot_sync(0xffffffffu, sup);
            if (lane == 0) {
                unsigned kept = 0u, alive = ~cur_sup;
#pragma unroll
                for (int b = 0; b < 32; b++) {
                    unsigned bit = 1u << b;
                    if (alive & bit) { kept |= bit; alive &= ~rows[b]; }
                }
                keepw[w2] = kept;
            }
        }
        __syncthreads();
        sup = sup || ((colw & keepw[w2]) != 0u);
    }
    // compact kept gt boxes
    bool keep = (keepw[w] >> lane) & 1u;
    unsigned wb = __ballot_sync(0xffffffffu, keep);
    if (lane == 0) warpoff[w] = __popc(wb);
    __syncthreads();
    if (j == 0) {
        int acc = 0;
#pragma unroll
        for (int k = 0; k < 32; k++) { int c = warpoff[k]; warpoff[k] = acc; acc += c; }
        d_Scnt = acc;
    }
    __syncthreads();
    if (keep) {
        int pos = warpoff[w] + __popc(wb & ((1u << lane) - 1u));
        int jo = d_order[j];
        d_joK[pos] = jo;
        d_geomK[pos] = d_geomGo[j];
        float4 cc = d_ccGo[j];
        d_ccK[pos] = make_float4(cc.x, cc.y, cc.z, d_gvol[jo]);
        d_zK[pos] = make_float2(d_gzmin[jo], d_gzmax[jo]);
    }
}

// fused iou3d row over COMPACT kept list: filter -> clip -> argmax -> outputs
__global__ void iou_fused_kernel(const float* __restrict__ labels,
                                 const float* __restrict__ cls,
                                 float* __restrict__ out) {
    __shared__ int s_pairs[1024];
    __shared__ int s_cnt;
    __shared__ unsigned long long s_best;
    int i = blockIdx.x, t = threadIdx.x;
    if (t == 0) { s_cnt = 0; s_best = 0xFFFFFFFFull; }  // iou=0.0, j=0
    __syncthreads();
    float4 ci = d_ccP[i];
    float amin = d_pzmin[i], amax = d_pzmax[i];
    int S = d_Scnt;
    for (int k = t; k < S; k += 256) {
        float2 z = d_zK[k];
        float oh = fminf(amax, z.y) - fmaxf(amin, z.x);
        if (oh > 0.f) {
            float4 cj = d_ccK[k];
            float dx = ci.x - cj.x, dy = ci.y - cj.y;
            float rr = ci.z + cj.z;
            if (dx * dx + dy * dy <= rr * rr)
                s_pairs[atomicAdd(&s_cnt, 1)] = k;
        }
    }
    __syncthreads();
    int cnt = s_cnt;
    if (cnt > 0) {
        Geom A = d_geomP[i];
        float va = d_pvol[i];
        for (int p = t; p < cnt; p += 256) {
            int k = s_pairs[p];
            Geom B = d_geomK[k];
            float2 z = d_zK[k];
            float oh = fminf(amax, z.y) - fmaxf(amin, z.x);
            float inter = rect_inter_sh(A, B) * oh;
            float un = fmaxf(va + d_ccK[k].w - inter, EPSF);
            float iou = inter / un;
            if (iou > 0.f) {
                int jo = d_joK[k];
                unsigned long long key =
                    (((unsigned long long)__float_as_uint(iou)) << 32) |
                    (unsigned long long)(0xFFFFFFFFu - (unsigned)jo);
                atomicMax(&s_best, key);
            }
        }
    }
    __syncthreads();
    if (t == 0) {
        unsigned long long key = s_best;
        float mo = __uint_as_float((unsigned)(key >> 32));
        int jb = (int)(0xFFFFFFFFu - (unsigned)(key & 0xFFFFFFFFull));
        mo = (mo > 0.75f) ? 1.0f : ((mo < 0.25f) ? 0.0f : mo);
        float lab = labels[i];
        float cp = 1.f / (1.f + expf(-cls[i]));
        out[i]         = (cp > 0.55f && lab > 0.55f) ? 1.0f : 0.0f;
        out[N + i]     = lab;
        out[2 * N + i] = mo;
        out[3 * N + i] = (float)jb;
    }
}

extern "C" void kernel_launch(void* const* d_in, const int* in_sizes, int n_in,
                              void* d_out, int out_size) {
    const float* labels = (const float*)d_in[0];
    const float* pred   = (const float*)d_in[1];
    const float* gt     = (const float*)d_in[2];
    const float* cls    = (const float*)d_in[3];
    if (n_in >= 3 && in_sizes[1] == 8 * N && in_sizes[2] == 7 * N) {
        pred = (const float*)d_in[2];
        gt   = (const float*)d_in[1];
    }
    float* out = (float*)d_out;

    prep_rank_kernel<<<N + 8, 256>>>(pred, gt, labels);
    nms_fused_kernel<<<N, 256>>>();
    nms_gs_kernel<<<1, 1024>>>();
    iou_fused_kernel<<<N, 256>>>(labels, cls, out);
}